// round 14
// baseline (speedup 1.0000x reference)
#include <cuda_runtime.h>
#include <math.h>

// GraphTemporalRefiner — R12 structure with SL=32 (halved per-block critical
// path; 1056 blocks still one resident wave).
//   y[b,n,t] = w[b,n] . x[b,t];  score_t = (1/rs) sum wv*y_{t+dd}
//   u_part   = sum_tau c_tau x_tau   (c = transpose-conv of phat/rs)
//   tail: o = Vp u + vb; a = out_proj o; LN; gelu MLP -> out (B,2)
// pre (grid 40): per-batch w chain + Vp/vb folding.
// score (grid (NS+1) x 32): s<NS slice blocks; s==NS prefetching tail block.

namespace {
constexpr int Bn  = 32;
constexpr int Tn  = 1024;
constexpr int Dn  = 64;
constexpr int Hn  = 128;
constexpr int NHn = 4;
constexpr int SL  = 32;
constexpr int NS  = Tn / SL;    // 32
constexpr int NR  = SL + 6;     // 38 rows incl. halo
constexpr int RS  = 71;         // xr scalar row stride (71%32=7 -> conflict-free)
}

__device__ float g_w[Bn * NHn * Dn];
__device__ float g_Vp[Hn * Dn];
__device__ float g_vb[Hn];
__device__ float g_m[Bn * NHn * NS];
__device__ float g_l[Bn * NHn * NS];
__device__ float g_u[Bn * NHn * NS * Dn];
__device__ unsigned int g_cnt[Bn];

__device__ __forceinline__ void l2_prefetch(const void* p) {
    asm volatile("prefetch.global.L2 [%0];" :: "l"(p));
}

// ---------------------------------------------------------------------------
// pre: blocks 0..31 -> w[b]; blocks 32..39 -> Vp rows (16 each) + vb.
// ---------------------------------------------------------------------------
__global__ void __launch_bounds__(256) pre_kernel(
    const float* __restrict__ x,
    const float* __restrict__ theta_w,    // (128, 64)
    const float* __restrict__ theta_b,
    const float* __restrict__ in_proj_w,  // (384, 128)
    const float* __restrict__ in_proj_b)
{
    const int tid = threadIdx.x;
    const int warp = tid >> 5, lane = tid & 31;
    const float SCALE = 0.17677669529663687f;   // 1/sqrt(32)

    __shared__ float th[Hn * (Dn + 1)];

    for (int i = tid; i < Hn * Dn; i += 256)
        th[(i >> 6) * (Dn + 1) + (i & 63)] = theta_w[i];

    if (blockIdx.x < Bn) {
        const int b = blockIdx.x;
        __shared__ float sxl[Dn];
        __shared__ float s_g[Hn];
        __shared__ float s_q[Hn];
        __shared__ float s_p[NHn][Hn];

        if (tid == 0) g_cnt[b] = 0u;

        if (tid < Dn) {                   // xl = conv at t = T-1
            float sum = 0.f, ws = 0.f;
#pragma unroll
            for (int dd = 0; dd < 4; dd++) {
                float wv = 1.0f / (1.0f + (float)dd);
                ws += wv;
                sum += wv * __ldg(&x[((size_t)b * Tn + (Tn - 1 - dd)) * Dn + tid]);
            }
            sxl[tid] = __fdividef(sum, ws);
        }
        __syncthreads();

        if (tid < Hn) {                   // g_last
            float acc = theta_b[tid];
#pragma unroll 8
            for (int d = 0; d < Dn; d++) acc += th[tid * (Dn + 1) + d] * sxl[d];
            s_g[tid] = acc;
        }
        __syncthreads();

#pragma unroll
        for (int k = 0; k < 16; k++) {    // q — warp per output
            int i = warp + 8 * k;
            float acc = 0.f;
#pragma unroll
            for (int m = 0; m < 4; m++)
                acc += __ldg(&in_proj_w[i * Hn + lane + 32 * m]) * s_g[lane + 32 * m];
#pragma unroll
            for (int off = 16; off; off >>= 1)
                acc += __shfl_xor_sync(0xFFFFFFFFu, acc, off);
            if (lane == 0) s_q[i] = acc + in_proj_b[i];
        }
        __syncthreads();

#pragma unroll
        for (int k = 0; k < 2; k++) {     // p[n][c]
            int o = tid + k * 256;
            int n = o >> 7, c = o & (Hn - 1);
            float acc = 0.f;
#pragma unroll 8
            for (int j = 0; j < 32; j++)
                acc += s_q[n * 32 + j] * __ldg(&in_proj_w[(Hn + n * 32 + j) * Hn + c]);
            s_p[n][c] = acc;
        }
        __syncthreads();

        {                                 // w[n][d]
            int n = tid >> 6, d = tid & 63;
            float acc = 0.f;
#pragma unroll 8
            for (int c = 0; c < Hn; c++) acc += s_p[n][c] * th[c * (Dn + 1) + d];
            g_w[b * (NHn * Dn) + tid] = acc * SCALE;
        }
    } else {
        const int r0 = (blockIdx.x - Bn) * 16;
        __shared__ float s_wv[16 * Hn];
        for (int i = tid; i < 16 * Hn; i += 256)
            s_wv[i] = in_proj_w[(2 * Hn + r0) * Hn + i];
        __syncthreads();
#pragma unroll
        for (int k = 0; k < 4; k++) {
            int o = tid + k * 256;
            int h = o >> 6, d = o & 63;
            float acc = 0.f;
#pragma unroll 8
            for (int c = 0; c < Hn; c++)
                acc += s_wv[h * Hn + c] * th[c * (Dn + 1) + d];
            g_Vp[(r0 + h) * Dn + d] = acc;
        }
        if (tid < 16) {
            float acc = in_proj_b[2 * Hn + r0 + tid];
#pragma unroll 8
            for (int c = 0; c < Hn; c++)
                acc += s_wv[tid * Hn + c] * theta_b[c];
            g_vb[r0 + tid] = acc;
        }
    }
}

// ---------------------------------------------------------------------------
// score: grid (NS+1, Bn). s<NS = slice body; s==NS = dedicated tail block.
// ---------------------------------------------------------------------------
__global__ void __launch_bounds__(256) score_kernel(
    const float* __restrict__ x,
    const float* __restrict__ out_proj_w,
    const float* __restrict__ out_proj_b,
    const float* __restrict__ ln_g,
    const float* __restrict__ ln_b,
    const float* __restrict__ w1,
    const float* __restrict__ b1,
    const float* __restrict__ w2,
    const float* __restrict__ b2,
    float* __restrict__ out)
{
    const int s = blockIdx.x, b = blockIdx.y, tid = threadIdx.x;
    const int warp = tid >> 5, lane = tid & 31;

    __shared__ float xr[NR * RS];        // ~10.8 KB
    __shared__ float y[NHn][NR + 2];
    __shared__ float sc[NHn][SL];
    __shared__ float rsinv[SL];
    __shared__ float cc[NHn][NR];
    __shared__ float sw[NHn][Dn + 1];
    __shared__ float s_ML[NHn][2];
    __shared__ float s_u[NHn * Dn];
    __shared__ float s_o[Hn];
    __shared__ float s_a[Hn];
    __shared__ float s_hid[Hn];
    __shared__ float s_mv[2];

    if (s < NS) {
        // ===================== slice body =====================
        const int t0 = s * SL;

        // stage raw x rows -> scalar stride-71 smem; OOB zeroed.
        // NR*16 = 608 float4; 3 per thread, issued back-to-back (MLP=3).
        {
            const float4* xb4 = (const float4*)&x[(size_t)b * Tn * Dn];
            float4 v[3];
            int idx[3];
#pragma unroll
            for (int k = 0; k < 3; k++) {
                int i = tid + k * 256;
                idx[k] = i;
                v[k] = make_float4(0.f, 0.f, 0.f, 0.f);
                if (i < NR * 16) {
                    int r = i >> 4, c4 = i & 15, gt = t0 - 3 + r;
                    if (gt >= 0 && gt < Tn) v[k] = __ldg(&xb4[gt * 16 + c4]);
                }
            }
#pragma unroll
            for (int k = 0; k < 3; k++) {
                int i = idx[k];
                if (i < NR * 16) {
                    int r = i >> 4, c4 = i & 15;
                    int base = r * RS + c4 * 4;
                    xr[base] = v[k].x; xr[base + 1] = v[k].y;
                    xr[base + 2] = v[k].z; xr[base + 3] = v[k].w;
                }
            }
        }
        sw[tid >> 6][tid & 63] = __ldg(&g_w[b * (NHn * Dn) + tid]);
        __syncthreads();

        // y[n][r] = w[n] . xr[r] — per-thread conflict-free dots (152 outputs)
        if (tid < NHn * NR) {
            int n = tid / NR, r = tid - n * NR;
            float acc = 0.f;
#pragma unroll 8
            for (int d = 0; d < Dn; d++) acc += sw[n][d] * xr[r * RS + d];
            y[n][r] = acc;
        }
        __syncthreads();

        // score_t = (1/rs) sum_dd wv y[t+3+dd]  (128 threads: n = tid>>5)
        if (tid < NHn * SL) {
            int n = tid >> 5, t = tid & 31, tg = t0 + t;
            float acc = 0.f, ws = 0.f;
#pragma unroll
            for (int dd = -3; dd <= 3; dd++) {
                int tt = tg + dd;
                if (tt >= 0 && tt < Tn) {
                    float wv = 1.0f / (1.0f + (float)(dd < 0 ? -dd : dd));
                    ws += wv;
                    acc += wv * y[n][t + 3 + dd];
                }
            }
            float inv = __fdividef(1.0f, ws);
            sc[n][t] = acc * inv;
            if (n == 0) rsinv[t] = inv;
        }
        __syncthreads();

        // slice softmax partials: warp n = head n (32 elems = 1/lane)
        if (tid < NHn * 32) {
            int n = tid >> 5;
            float v0 = sc[n][lane];
            float m = v0;
#pragma unroll
            for (int off = 16; off; off >>= 1)
                m = fmaxf(m, __shfl_xor_sync(0xFFFFFFFFu, m, off));
            float e0 = __expf(v0 - m);
            sc[n][lane] = e0;
            float l = e0;
#pragma unroll
            for (int off = 16; off; off >>= 1)
                l += __shfl_xor_sync(0xFFFFFFFFu, l, off);
            if (lane == 0) {
                g_m[(b * NHn + n) * NS + s] = m;
                g_l[(b * NHn + n) * NS + s] = l;
            }
        }
        __syncthreads();

        // c[n][i] = transpose-conv of phat*rsinv (152 outputs)
        if (tid < NHn * NR) {
            int n = tid / NR, i = tid - n * NR;
            int taug = t0 - 3 + i;
            float acc = 0.f;
            if (taug >= 0 && taug < Tn) {
#pragma unroll
                for (int dd = -3; dd <= 3; dd++) {
                    int j = i - 3 - dd;
                    if (j >= 0 && j < SL) {
                        float wv = 1.0f / (1.0f + (float)(dd < 0 ? -dd : dd));
                        acc += wv * sc[n][j] * rsinv[j];
                    }
                }
            }
            cc[n][i] = acc;
        }
        __syncthreads();

        // u_part[n][d] = sum_i c[n][i] * xr[i][d]  (38-iter loop)
        {
            int n = tid >> 6, d = tid & 63;
            float acc = 0.f;
#pragma unroll 19
            for (int i = 0; i < NR; i++) acc += cc[n][i] * xr[i * RS + d];
            g_u[((b * NHn + n) * NS + s) * Dn + d] = acc;
        }

        // release: syncthreads orders all stores, tid0 fence+atomic publishes.
        __syncthreads();
        if (tid == 0) {
            __threadfence();
            atomicAdd(&g_cnt[b], 1u);
        }
        return;
    }

    // ===================== dedicated tail block (s == NS) =====================
    // L2-prefetch tail weights while slices run
    {
        const char* p1 = (const char*)out_proj_w;    // 64 KB
        const char* p2 = (const char*)w1;            // 64 KB
        const char* p3 = (const char*)g_Vp;          // 32 KB
        for (int i = tid; i < 512; i += 256) { l2_prefetch(p1 + i * 128); l2_prefetch(p2 + i * 128); }
        for (int i = tid; i < 256; i += 256) l2_prefetch(p3 + i * 128);
        if (tid < 8) {
            l2_prefetch((const char*)g_vb + tid * 64);
            l2_prefetch((const char*)out_proj_b + tid * 64);
            l2_prefetch((const char*)ln_g + tid * 64);
            l2_prefetch((const char*)ln_b + tid * 64);
            l2_prefetch((const char*)b1 + tid * 64);
            l2_prefetch((const char*)w2 + tid * 64);
        }
    }

    // spin until all NS slice blocks of this batch have deposited partials
    if (tid == 0) {
        volatile unsigned int* cnt = &g_cnt[b];
        while (*cnt < (unsigned)NS) __nanosleep(128);
    }
    __syncthreads();
    __threadfence();   // acquire

    if (tid < NHn) {
        float M = -1e30f;
#pragma unroll
        for (int k = 0; k < NS; k++) M = fmaxf(M, g_m[(b * NHn + tid) * NS + k]);
        float L = 0.f;
#pragma unroll
        for (int k = 0; k < NS; k++)
            L += g_l[(b * NHn + tid) * NS + k] *
                 __expf(g_m[(b * NHn + tid) * NS + k] - M);
        s_ML[tid][0] = M;
        s_ML[tid][1] = L;
    }
    __syncthreads();
    {
        int n = tid >> 6, d = tid & 63;
        float acc = 0.f;
#pragma unroll
        for (int k = 0; k < NS; k++)
            acc += g_u[((b * NHn + n) * NS + k) * Dn + d] *
                   __expf(g_m[(b * NHn + n) * NS + k] - s_ML[n][0]);
        s_u[n * Dn + d] = __fdividef(acc, s_ML[n][1]);
    }
    __syncthreads();

    // o[i] = vb[i] + Vp[i,:] . u[i/32] — warp per output
#pragma unroll
    for (int k = 0; k < 16; k++) {
        int i = warp + 8 * k;
        int n = i >> 5;
        float acc = 0.f;
#pragma unroll
        for (int m = 0; m < 2; m++)
            acc += __ldg(&g_Vp[i * Dn + lane + 32 * m]) * s_u[n * Dn + lane + 32 * m];
#pragma unroll
        for (int off = 16; off; off >>= 1)
            acc += __shfl_xor_sync(0xFFFFFFFFu, acc, off);
        if (lane == 0) s_o[i] = acc + g_vb[i];
    }
    __syncthreads();

    // a[i] = out_proj[i,:] . o + b — warp per output
#pragma unroll
    for (int k = 0; k < 16; k++) {
        int i = warp + 8 * k;
        float acc = 0.f;
#pragma unroll
        for (int m = 0; m < 4; m++)
            acc += __ldg(&out_proj_w[i * Hn + lane + 32 * m]) * s_o[lane + 32 * m];
#pragma unroll
        for (int off = 16; off; off >>= 1)
            acc += __shfl_xor_sync(0xFFFFFFFFu, acc, off);
        if (lane == 0) s_a[i] = acc + out_proj_b[i];
    }
    __syncthreads();

    // LayerNorm over 128
    if (tid < 32) {
        float sum = s_a[tid] + s_a[tid + 32] + s_a[tid + 64] + s_a[tid + 96];
#pragma unroll
        for (int off = 16; off; off >>= 1)
            sum += __shfl_xor_sync(0xFFFFFFFFu, sum, off);
        if (tid == 0) s_mv[0] = sum * (1.0f / Hn);
    }
    __syncthreads();
    if (tid < 32) {
        float mu = s_mv[0], sum = 0.f;
#pragma unroll
        for (int k = 0; k < 4; k++) {
            float d = s_a[tid + 32 * k] - mu;
            sum += d * d;
        }
#pragma unroll
        for (int off = 16; off; off >>= 1)
            sum += __shfl_xor_sync(0xFFFFFFFFu, sum, off);
        if (tid == 0) s_mv[1] = sum * (1.0f / Hn);
    }
    __syncthreads();
    if (tid < Hn) {
        float inv = rsqrtf(s_mv[1] + 1e-5f);
        s_a[tid] = (s_a[tid] - s_mv[0]) * inv * ln_g[tid] + ln_b[tid];
    }
    __syncthreads();

    // hid = gelu(w1 @ ln + b1) — warp per output
#pragma unroll
    for (int k = 0; k < 16; k++) {
        int i = warp + 8 * k;
        float acc = 0.f;
#pragma unroll
        for (int m = 0; m < 4; m++)
            acc += __ldg(&w1[i * Hn + lane + 32 * m]) * s_a[lane + 32 * m];
#pragma unroll
        for (int off = 16; off; off >>= 1)
            acc += __shfl_xor_sync(0xFFFFFFFFu, acc, off);
        if (lane == 0) {
            float v = acc + b1[i];
            s_hid[i] = 0.5f * v * (1.0f + erff(v * 0.70710678118654752f));
        }
    }
    __syncthreads();

    if (warp < 2) {
        float acc = 0.f;
#pragma unroll
        for (int m = 0; m < 4; m++)
            acc += __ldg(&w2[warp * Hn + lane + 32 * m]) * s_hid[lane + 32 * m];
#pragma unroll
        for (int off = 16; off; off >>= 1)
            acc += __shfl_xor_sync(0xFFFFFFFFu, acc, off);
        if (lane == 0) out[b * 2 + warp] = acc + b2[warp];
    }

    // reset counter for next graph replay
    __syncthreads();
    if (tid == 0) g_cnt[b] = 0u;
}

// ---------------------------------------------------------------------------
extern "C" void kernel_launch(void* const* d_in, const int* in_sizes, int n_in,
                              void* d_out, int out_size) {
    const float* x          = (const float*)d_in[0];
    const float* theta_w    = (const float*)d_in[1];
    const float* theta_b    = (const float*)d_in[2];
    const float* in_proj_w  = (const float*)d_in[3];
    const float* in_proj_b  = (const float*)d_in[4];
    const float* out_proj_w = (const float*)d_in[5];
    const float* out_proj_b = (const float*)d_in[6];
    const float* lng        = (const float*)d_in[7];
    const float* lnb        = (const float*)d_in[8];
    const float* w1         = (const float*)d_in[9];
    const float* b1         = (const float*)d_in[10];
    const float* w2         = (const float*)d_in[11];
    const float* b2         = (const float*)d_in[12];
    float* out = (float*)d_out;

    pre_kernel<<<40, 256>>>(x, theta_w, theta_b, in_proj_w, in_proj_b);
    score_kernel<<<dim3(NS + 1, Bn), 256>>>(x, out_proj_w, out_proj_b,
                                            lng, lnb, w1, b1, w2, b2, out);
}

// round 15
// speedup vs baseline: 1.1337x; 1.1337x over previous
#include <cuda_runtime.h>
#include <math.h>

// GraphTemporalRefiner — R12 (best) + 4-way interleaved warp-dot GEMVs in
// pre's q-phase and the tail stages (16 serialized memory latencies -> 1).
//   y[b,n,t] = w[b,n] . x[b,t];  score_t = (1/rs) sum wv*y_{t+dd}
//   u_part   = sum_tau c_tau x_tau   (c = transpose-conv of phat/rs)
//   tail: o = Vp u + vb; a = out_proj o; LN; gelu MLP -> out (B,2)
// pre (grid 40): per-batch w chain + Vp/vb folding.
// score (grid (NS+1) x 32): s<NS slice blocks; s==NS prefetching tail block.

namespace {
constexpr int Bn  = 32;
constexpr int Tn  = 1024;
constexpr int Dn  = 64;
constexpr int Hn  = 128;
constexpr int NHn = 4;
constexpr int SL  = 64;
constexpr int NS  = Tn / SL;    // 16
constexpr int NR  = SL + 6;     // 70 rows incl. halo
constexpr int RS  = 71;         // xr scalar row stride (71%32=7 -> conflict-free)
}

__device__ float g_w[Bn * NHn * Dn];
__device__ float g_Vp[Hn * Dn];
__device__ float g_vb[Hn];
__device__ float g_m[Bn * NHn * NS];
__device__ float g_l[Bn * NHn * NS];
__device__ float g_u[Bn * NHn * NS * Dn];
__device__ unsigned int g_cnt[Bn];

__device__ __forceinline__ void l2_prefetch(const void* p) {
    asm volatile("prefetch.global.L2 [%0];" :: "l"(p));
}

// ---------------------------------------------------------------------------
// pre: blocks 0..31 -> w[b]; blocks 32..39 -> Vp rows (16 each) + vb.
// ---------------------------------------------------------------------------
__global__ void __launch_bounds__(256) pre_kernel(
    const float* __restrict__ x,
    const float* __restrict__ theta_w,    // (128, 64)
    const float* __restrict__ theta_b,
    const float* __restrict__ in_proj_w,  // (384, 128)
    const float* __restrict__ in_proj_b)
{
    const int tid = threadIdx.x;
    const int warp = tid >> 5, lane = tid & 31;
    const float SCALE = 0.17677669529663687f;   // 1/sqrt(32)

    __shared__ float th[Hn * (Dn + 1)];

    for (int i = tid; i < Hn * Dn; i += 256)
        th[(i >> 6) * (Dn + 1) + (i & 63)] = theta_w[i];

    if (blockIdx.x < Bn) {
        const int b = blockIdx.x;
        __shared__ float sxl[Dn];
        __shared__ float s_g[Hn];
        __shared__ float s_q[Hn];
        __shared__ float s_p[NHn][Hn];

        if (tid == 0) g_cnt[b] = 0u;

        if (tid < Dn) {                   // xl = conv at t = T-1
            float sum = 0.f, ws = 0.f;
#pragma unroll
            for (int dd = 0; dd < 4; dd++) {
                float wv = 1.0f / (1.0f + (float)dd);
                ws += wv;
                sum += wv * __ldg(&x[((size_t)b * Tn + (Tn - 1 - dd)) * Dn + tid]);
            }
            sxl[tid] = __fdividef(sum, ws);
        }
        __syncthreads();

        if (tid < Hn) {                   // g_last
            float acc = theta_b[tid];
#pragma unroll 8
            for (int d = 0; d < Dn; d++) acc += th[tid * (Dn + 1) + d] * sxl[d];
            s_g[tid] = acc;
        }
        __syncthreads();

        // q — 4-way interleaved warp-dots (16 loads in flight per warp)
#pragma unroll
        for (int gq = 0; gq < 4; gq++) {
            int i0 = warp + 8 * (4 * gq + 0);
            int i1 = warp + 8 * (4 * gq + 1);
            int i2 = warp + 8 * (4 * gq + 2);
            int i3 = warp + 8 * (4 * gq + 3);
            float a0 = 0.f, a1 = 0.f, a2 = 0.f, a3 = 0.f;
#pragma unroll
            for (int m = 0; m < 4; m++) {
                float gm = s_g[lane + 32 * m];
                a0 += __ldg(&in_proj_w[i0 * Hn + lane + 32 * m]) * gm;
                a1 += __ldg(&in_proj_w[i1 * Hn + lane + 32 * m]) * gm;
                a2 += __ldg(&in_proj_w[i2 * Hn + lane + 32 * m]) * gm;
                a3 += __ldg(&in_proj_w[i3 * Hn + lane + 32 * m]) * gm;
            }
#pragma unroll
            for (int off = 16; off; off >>= 1) {
                a0 += __shfl_xor_sync(0xFFFFFFFFu, a0, off);
                a1 += __shfl_xor_sync(0xFFFFFFFFu, a1, off);
                a2 += __shfl_xor_sync(0xFFFFFFFFu, a2, off);
                a3 += __shfl_xor_sync(0xFFFFFFFFu, a3, off);
            }
            if (lane == 0) {
                s_q[i0] = a0 + in_proj_b[i0];
                s_q[i1] = a1 + in_proj_b[i1];
                s_q[i2] = a2 + in_proj_b[i2];
                s_q[i3] = a3 + in_proj_b[i3];
            }
        }
        __syncthreads();

#pragma unroll
        for (int k = 0; k < 2; k++) {     // p[n][c] — coalesced over c
            int o = tid + k * 256;
            int n = o >> 7, c = o & (Hn - 1);
            float acc = 0.f;
#pragma unroll 16
            for (int j = 0; j < 32; j++)
                acc += s_q[n * 32 + j] * __ldg(&in_proj_w[(Hn + n * 32 + j) * Hn + c]);
            s_p[n][c] = acc;
        }
        __syncthreads();

        {                                 // w[n][d]
            int n = tid >> 6, d = tid & 63;
            float acc = 0.f;
#pragma unroll 8
            for (int c = 0; c < Hn; c++) acc += s_p[n][c] * th[c * (Dn + 1) + d];
            g_w[b * (NHn * Dn) + tid] = acc * SCALE;
        }
    } else {
        const int r0 = (blockIdx.x - Bn) * 16;
        __shared__ float s_wv[16 * Hn];
        for (int i = tid; i < 16 * Hn; i += 256)
            s_wv[i] = in_proj_w[(2 * Hn + r0) * Hn + i];
        __syncthreads();
#pragma unroll
        for (int k = 0; k < 4; k++) {
            int o = tid + k * 256;
            int h = o >> 6, d = o & 63;
            float acc = 0.f;
#pragma unroll 8
            for (int c = 0; c < Hn; c++)
                acc += s_wv[h * Hn + c] * th[c * (Dn + 1) + d];
            g_Vp[(r0 + h) * Dn + d] = acc;
        }
        if (tid < 16) {
            float acc = in_proj_b[2 * Hn + r0 + tid];
#pragma unroll 8
            for (int c = 0; c < Hn; c++)
                acc += s_wv[tid * Hn + c] * theta_b[c];
            g_vb[r0 + tid] = acc;
        }
    }
}

// ---------------------------------------------------------------------------
// score: grid (NS+1, Bn). s<NS = slice body; s==NS = dedicated tail block.
// ---------------------------------------------------------------------------
__global__ void __launch_bounds__(256) score_kernel(
    const float* __restrict__ x,
    const float* __restrict__ out_proj_w,
    const float* __restrict__ out_proj_b,
    const float* __restrict__ ln_g,
    const float* __restrict__ ln_b,
    const float* __restrict__ w1,
    const float* __restrict__ b1,
    const float* __restrict__ w2,
    const float* __restrict__ b2,
    float* __restrict__ out)
{
    const int s = blockIdx.x, b = blockIdx.y, tid = threadIdx.x;
    const int warp = tid >> 5, lane = tid & 31;

    __shared__ float xr[NR * RS];
    __shared__ float y[NHn][NR + 2];
    __shared__ float sc[NHn][SL];
    __shared__ float rsinv[SL];
    __shared__ float cc[NHn][NR];
    __shared__ float sw[NHn][Dn + 1];
    __shared__ float s_ML[NHn][2];
    __shared__ float s_u[NHn * Dn];
    __shared__ float s_o[Hn];
    __shared__ float s_a[Hn];
    __shared__ float s_hid[Hn];
    __shared__ float s_mv[2];

    if (s < NS) {
        // ===================== slice body (byte-identical to R12) ==========
        const int t0 = s * SL;
        {
            const float4* xb4 = (const float4*)&x[(size_t)b * Tn * Dn];
            float4 v[5];
            int idx[5];
#pragma unroll
            for (int k = 0; k < 5; k++) {
                int i = tid + k * 256;
                idx[k] = i;
                v[k] = make_float4(0.f, 0.f, 0.f, 0.f);
                if (i < NR * 16) {
                    int r = i >> 4, c4 = i & 15, gt = t0 - 3 + r;
                    if (gt >= 0 && gt < Tn) v[k] = __ldg(&xb4[gt * 16 + c4]);
                }
            }
#pragma unroll
            for (int k = 0; k < 5; k++) {
                int i = idx[k];
                if (i < NR * 16) {
                    int r = i >> 4, c4 = i & 15;
                    int base = r * RS + c4 * 4;
                    xr[base] = v[k].x; xr[base + 1] = v[k].y;
                    xr[base + 2] = v[k].z; xr[base + 3] = v[k].w;
                }
            }
        }
        sw[tid >> 6][tid & 63] = __ldg(&g_w[b * (NHn * Dn) + tid]);
        __syncthreads();

        for (int o = tid; o < NHn * NR; o += 256) {
            int n = o / NR, r = o - n * NR;
            float acc = 0.f;
#pragma unroll 8
            for (int d = 0; d < Dn; d++) acc += sw[n][d] * xr[r * RS + d];
            y[n][r] = acc;
        }
        __syncthreads();

        {
            int n = tid >> 6, t = tid & 63, tg = t0 + t;
            float acc = 0.f, ws = 0.f;
#pragma unroll
            for (int dd = -3; dd <= 3; dd++) {
                int tt = tg + dd;
                if (tt >= 0 && tt < Tn) {
                    float wv = 1.0f / (1.0f + (float)(dd < 0 ? -dd : dd));
                    ws += wv;
                    acc += wv * y[n][t + 3 + dd];
                }
            }
            float inv = __fdividef(1.0f, ws);
            sc[n][t] = acc * inv;
            if (n == 0) rsinv[t] = inv;
        }
        __syncthreads();

        if (tid < NHn * 32) {
            int n = tid >> 5;
            float v0 = sc[n][lane], v1 = sc[n][lane + 32];
            float m = fmaxf(v0, v1);
#pragma unroll
            for (int off = 16; off; off >>= 1)
                m = fmaxf(m, __shfl_xor_sync(0xFFFFFFFFu, m, off));
            float e0 = __expf(v0 - m), e1 = __expf(v1 - m);
            sc[n][lane] = e0; sc[n][lane + 32] = e1;
            float l = e0 + e1;
#pragma unroll
            for (int off = 16; off; off >>= 1)
                l += __shfl_xor_sync(0xFFFFFFFFu, l, off);
            if (lane == 0) {
                g_m[(b * NHn + n) * NS + s] = m;
                g_l[(b * NHn + n) * NS + s] = l;
            }
        }
        __syncthreads();

        for (int o = tid; o < NHn * NR; o += 256) {
            int n = o / NR, i = o - n * NR;
            int taug = t0 - 3 + i;
            float acc = 0.f;
            if (taug >= 0 && taug < Tn) {
#pragma unroll
                for (int dd = -3; dd <= 3; dd++) {
                    int j = i - 3 - dd;
                    if (j >= 0 && j < SL) {
                        float wv = 1.0f / (1.0f + (float)(dd < 0 ? -dd : dd));
                        acc += wv * sc[n][j] * rsinv[j];
                    }
                }
            }
            cc[n][i] = acc;
        }
        __syncthreads();

        {
            int n = tid >> 6, d = tid & 63;
            float acc = 0.f;
#pragma unroll 7
            for (int i = 0; i < NR; i++) acc += cc[n][i] * xr[i * RS + d];
            g_u[((b * NHn + n) * NS + s) * Dn + d] = acc;
        }

        __syncthreads();
        if (tid == 0) {
            __threadfence();
            atomicAdd(&g_cnt[b], 1u);
        }
        return;
    }

    // ===================== dedicated tail block (s == NS) =====================
    {
        const char* p1 = (const char*)out_proj_w;    // 64 KB
        const char* p2 = (const char*)w1;            // 64 KB
        const char* p3 = (const char*)g_Vp;          // 32 KB
        for (int i = tid; i < 512; i += 256) { l2_prefetch(p1 + i * 128); l2_prefetch(p2 + i * 128); }
        for (int i = tid; i < 256; i += 256) l2_prefetch(p3 + i * 128);
        if (tid < 8) {
            l2_prefetch((const char*)g_vb + tid * 64);
            l2_prefetch((const char*)out_proj_b + tid * 64);
            l2_prefetch((const char*)ln_g + tid * 64);
            l2_prefetch((const char*)ln_b + tid * 64);
            l2_prefetch((const char*)b1 + tid * 64);
            l2_prefetch((const char*)w2 + tid * 64);
        }
    }

    if (tid == 0) {
        volatile unsigned int* cnt = &g_cnt[b];
        while (*cnt < (unsigned)NS) __nanosleep(128);
    }
    __syncthreads();
    __threadfence();   // acquire

    if (tid < NHn) {
        float M = -1e30f;
#pragma unroll
        for (int k = 0; k < NS; k++) M = fmaxf(M, g_m[(b * NHn + tid) * NS + k]);
        float L = 0.f;
#pragma unroll
        for (int k = 0; k < NS; k++)
            L += g_l[(b * NHn + tid) * NS + k] *
                 __expf(g_m[(b * NHn + tid) * NS + k] - M);
        s_ML[tid][0] = M;
        s_ML[tid][1] = L;
    }
    __syncthreads();
    {
        int n = tid >> 6, d = tid & 63;
        float acc = 0.f;
#pragma unroll
        for (int k = 0; k < NS; k++)
            acc += g_u[((b * NHn + n) * NS + k) * Dn + d] *
                   __expf(g_m[(b * NHn + n) * NS + k] - s_ML[n][0]);
        s_u[n * Dn + d] = __fdividef(acc, s_ML[n][1]);
    }
    __syncthreads();

    // o[i] = vb[i] + Vp[i,:] . u[i/32] — 4-way interleaved warp-dots
#pragma unroll
    for (int gq = 0; gq < 4; gq++) {
        int i0 = warp + 8 * (4 * gq + 0);
        int i1 = warp + 8 * (4 * gq + 1);
        int i2 = warp + 8 * (4 * gq + 2);
        int i3 = warp + 8 * (4 * gq + 3);
        float a0 = 0.f, a1 = 0.f, a2 = 0.f, a3 = 0.f;
#pragma unroll
        for (int m = 0; m < 2; m++) {
            int c = lane + 32 * m;
            a0 += __ldg(&g_Vp[i0 * Dn + c]) * s_u[(i0 >> 5) * Dn + c];
            a1 += __ldg(&g_Vp[i1 * Dn + c]) * s_u[(i1 >> 5) * Dn + c];
            a2 += __ldg(&g_Vp[i2 * Dn + c]) * s_u[(i2 >> 5) * Dn + c];
            a3 += __ldg(&g_Vp[i3 * Dn + c]) * s_u[(i3 >> 5) * Dn + c];
        }
#pragma unroll
        for (int off = 16; off; off >>= 1) {
            a0 += __shfl_xor_sync(0xFFFFFFFFu, a0, off);
            a1 += __shfl_xor_sync(0xFFFFFFFFu, a1, off);
            a2 += __shfl_xor_sync(0xFFFFFFFFu, a2, off);
            a3 += __shfl_xor_sync(0xFFFFFFFFu, a3, off);
        }
        if (lane == 0) {
            s_o[i0] = a0 + g_vb[i0];
            s_o[i1] = a1 + g_vb[i1];
            s_o[i2] = a2 + g_vb[i2];
            s_o[i3] = a3 + g_vb[i3];
        }
    }
    __syncthreads();

    // a[i] = out_proj[i,:] . o + b — 4-way interleaved warp-dots
#pragma unroll
    for (int gq = 0; gq < 4; gq++) {
        int i0 = warp + 8 * (4 * gq + 0);
        int i1 = warp + 8 * (4 * gq + 1);
        int i2 = warp + 8 * (4 * gq + 2);
        int i3 = warp + 8 * (4 * gq + 3);
        float a0 = 0.f, a1 = 0.f, a2 = 0.f, a3 = 0.f;
#pragma unroll
        for (int m = 0; m < 4; m++) {
            float ov = s_o[lane + 32 * m];
            a0 += __ldg(&out_proj_w[i0 * Hn + lane + 32 * m]) * ov;
            a1 += __ldg(&out_proj_w[i1 * Hn + lane + 32 * m]) * ov;
            a2 += __ldg(&out_proj_w[i2 * Hn + lane + 32 * m]) * ov;
            a3 += __ldg(&out_proj_w[i3 * Hn + lane + 32 * m]) * ov;
        }
#pragma unroll
        for (int off = 16; off; off >>= 1) {
            a0 += __shfl_xor_sync(0xFFFFFFFFu, a0, off);
            a1 += __shfl_xor_sync(0xFFFFFFFFu, a1, off);
            a2 += __shfl_xor_sync(0xFFFFFFFFu, a2, off);
            a3 += __shfl_xor_sync(0xFFFFFFFFu, a3, off);
        }
        if (lane == 0) {
            s_a[i0] = a0 + out_proj_b[i0];
            s_a[i1] = a1 + out_proj_b[i1];
            s_a[i2] = a2 + out_proj_b[i2];
            s_a[i3] = a3 + out_proj_b[i3];
        }
    }
    __syncthreads();

    // LayerNorm over 128
    if (tid < 32) {
        float sum = s_a[tid] + s_a[tid + 32] + s_a[tid + 64] + s_a[tid + 96];
#pragma unroll
        for (int off = 16; off; off >>= 1)
            sum += __shfl_xor_sync(0xFFFFFFFFu, sum, off);
        if (tid == 0) s_mv[0] = sum * (1.0f / Hn);
    }
    __syncthreads();
    if (tid < 32) {
        float mu = s_mv[0], sum = 0.f;
#pragma unroll
        for (int k = 0; k < 4; k++) {
            float d = s_a[tid + 32 * k] - mu;
            sum += d * d;
        }
#pragma unroll
        for (int off = 16; off; off >>= 1)
            sum += __shfl_xor_sync(0xFFFFFFFFu, sum, off);
        if (tid == 0) s_mv[1] = sum * (1.0f / Hn);
    }
    __syncthreads();
    if (tid < Hn) {
        float inv = rsqrtf(s_mv[1] + 1e-5f);
        s_a[tid] = (s_a[tid] - s_mv[0]) * inv * ln_g[tid] + ln_b[tid];
    }
    __syncthreads();

    // hid = gelu(w1 @ ln + b1) — 4-way interleaved warp-dots
#pragma unroll
    for (int gq = 0; gq < 4; gq++) {
        int i0 = warp + 8 * (4 * gq + 0);
        int i1 = warp + 8 * (4 * gq + 1);
        int i2 = warp + 8 * (4 * gq + 2);
        int i3 = warp + 8 * (4 * gq + 3);
        float a0 = 0.f, a1 = 0.f, a2 = 0.f, a3 = 0.f;
#pragma unroll
        for (int m = 0; m < 4; m++) {
            float lv = s_a[lane + 32 * m];
            a0 += __ldg(&w1[i0 * Hn + lane + 32 * m]) * lv;
            a1 += __ldg(&w1[i1 * Hn + lane + 32 * m]) * lv;
            a2 += __ldg(&w1[i2 * Hn + lane + 32 * m]) * lv;
            a3 += __ldg(&w1[i3 * Hn + lane + 32 * m]) * lv;
        }
#pragma unroll
        for (int off = 16; off; off >>= 1) {
            a0 += __shfl_xor_sync(0xFFFFFFFFu, a0, off);
            a1 += __shfl_xor_sync(0xFFFFFFFFu, a1, off);
            a2 += __shfl_xor_sync(0xFFFFFFFFu, a2, off);
            a3 += __shfl_xor_sync(0xFFFFFFFFu, a3, off);
        }
        if (lane == 0) {
            float v0 = a0 + b1[i0], v1 = a1 + b1[i1];
            float v2 = a2 + b1[i2], v3 = a3 + b1[i3];
            s_hid[i0] = 0.5f * v0 * (1.0f + erff(v0 * 0.70710678118654752f));
            s_hid[i1] = 0.5f * v1 * (1.0f + erff(v1 * 0.70710678118654752f));
            s_hid[i2] = 0.5f * v2 * (1.0f + erff(v2 * 0.70710678118654752f));
            s_hid[i3] = 0.5f * v3 * (1.0f + erff(v3 * 0.70710678118654752f));
        }
    }
    __syncthreads();

    if (warp < 2) {
        float acc = 0.f;
#pragma unroll
        for (int m = 0; m < 4; m++)
            acc += __ldg(&w2[warp * Hn + lane + 32 * m]) * s_hid[lane + 32 * m];
#pragma unroll
        for (int off = 16; off; off >>= 1)
            acc += __shfl_xor_sync(0xFFFFFFFFu, acc, off);
        if (lane == 0) out[b * 2 + warp] = acc + b2[warp];
    }

    // reset counter for next graph replay
    __syncthreads();
    if (tid == 0) g_cnt[b] = 0u;
}

// ---------------------------------------------------------------------------
extern "C" void kernel_launch(void* const* d_in, const int* in_sizes, int n_in,
                              void* d_out, int out_size) {
    const float* x          = (const float*)d_in[0];
    const float* theta_w    = (const float*)d_in[1];
    const float* theta_b    = (const float*)d_in[2];
    const float* in_proj_w  = (const float*)d_in[3];
    const float* in_proj_b  = (const float*)d_in[4];
    const float* out_proj_w = (const float*)d_in[5];
    const float* out_proj_b = (const float*)d_in[6];
    const float* lng        = (const float*)d_in[7];
    const float* lnb        = (const float*)d_in[8];
    const float* w1         = (const float*)d_in[9];
    const float* b1         = (const float*)d_in[10];
    const float* w2         = (const float*)d_in[11];
    const float* b2         = (const float*)d_in[12];
    float* out = (float*)d_out;

    pre_kernel<<<40, 256>>>(x, theta_w, theta_b, in_proj_w, in_proj_b);
    score_kernel<<<dim3(NS + 1, Bn), 256>>>(x, out_proj_w, out_proj_b,
                                            lng, lnb, w1, b1, w2, b2, out);
}

// round 16
// speedup vs baseline: 1.1982x; 1.0569x over previous
#include <cuda_runtime.h>
#include <math.h>

// GraphTemporalRefiner — R15 (best) + float4-vectorized weight staging in pre
// (32 serialized LDG->STS iterations -> 8 LDG.128 in flight).
//   y[b,n,t] = w[b,n] . x[b,t];  score_t = (1/rs) sum wv*y_{t+dd}
//   u_part   = sum_tau c_tau x_tau   (c = transpose-conv of phat/rs)
//   tail: o = Vp u + vb; a = out_proj o; LN; gelu MLP -> out (B,2)
// pre (grid 40): per-batch w chain + Vp/vb folding.
// score (grid (NS+1) x 32): s<NS slice blocks; s==NS prefetching tail block.

namespace {
constexpr int Bn  = 32;
constexpr int Tn  = 1024;
constexpr int Dn  = 64;
constexpr int Hn  = 128;
constexpr int NHn = 4;
constexpr int SL  = 64;
constexpr int NS  = Tn / SL;    // 16
constexpr int NR  = SL + 6;     // 70 rows incl. halo
constexpr int RS  = 71;         // xr scalar row stride (71%32=7 -> conflict-free)
constexpr int THS = Dn + 1;     // padded theta row stride (65)
}

__device__ float g_w[Bn * NHn * Dn];
__device__ float g_Vp[Hn * Dn];
__device__ float g_vb[Hn];
__device__ float g_m[Bn * NHn * NS];
__device__ float g_l[Bn * NHn * NS];
__device__ float g_u[Bn * NHn * NS * Dn];
__device__ unsigned int g_cnt[Bn];

__device__ __forceinline__ void l2_prefetch(const void* p) {
    asm volatile("prefetch.global.L2 [%0];" :: "l"(p));
}

// ---------------------------------------------------------------------------
// pre: blocks 0..31 -> w[b]; blocks 32..39 -> Vp rows (16 each) + vb.
// ---------------------------------------------------------------------------
__global__ void __launch_bounds__(256) pre_kernel(
    const float* __restrict__ x,
    const float* __restrict__ theta_w,    // (128, 64)
    const float* __restrict__ theta_b,
    const float* __restrict__ in_proj_w,  // (384, 128)
    const float* __restrict__ in_proj_b)
{
    const int tid = threadIdx.x;
    const int warp = tid >> 5, lane = tid & 31;
    const float SCALE = 0.17677669529663687f;   // 1/sqrt(32)

    __shared__ float th[Hn * THS];   // padded theta

    // theta staging: 2048 float4, 8 per thread, all loads in flight at once
    {
        const float4* th4 = (const float4*)theta_w;
        float4 v[8];
#pragma unroll
        for (int k = 0; k < 8; k++) v[k] = __ldg(&th4[tid + k * 256]);
#pragma unroll
        for (int k = 0; k < 8; k++) {
            int i = tid + k * 256;
            int r = i >> 4, c = (i & 15) * 4;
            int base = r * THS + c;
            th[base] = v[k].x; th[base + 1] = v[k].y;
            th[base + 2] = v[k].z; th[base + 3] = v[k].w;
        }
    }

    if (blockIdx.x < Bn) {
        const int b = blockIdx.x;
        __shared__ float sxl[Dn];
        __shared__ float s_g[Hn];
        __shared__ float s_q[Hn];
        __shared__ float s_p[NHn][Hn];

        if (tid == 0) g_cnt[b] = 0u;

        if (tid < Dn) {                   // xl = conv at t = T-1
            float sum = 0.f, ws = 0.f;
#pragma unroll
            for (int dd = 0; dd < 4; dd++) {
                float wv = 1.0f / (1.0f + (float)dd);
                ws += wv;
                sum += wv * __ldg(&x[((size_t)b * Tn + (Tn - 1 - dd)) * Dn + tid]);
            }
            sxl[tid] = __fdividef(sum, ws);
        }
        __syncthreads();

        if (tid < Hn) {                   // g_last
            float acc = theta_b[tid];
#pragma unroll 8
            for (int d = 0; d < Dn; d++) acc += th[tid * THS + d] * sxl[d];
            s_g[tid] = acc;
        }
        __syncthreads();

        // q — 4-way interleaved warp-dots (16 loads in flight per warp)
#pragma unroll
        for (int gq = 0; gq < 4; gq++) {
            int i0 = warp + 8 * (4 * gq + 0);
            int i1 = warp + 8 * (4 * gq + 1);
            int i2 = warp + 8 * (4 * gq + 2);
            int i3 = warp + 8 * (4 * gq + 3);
            float a0 = 0.f, a1 = 0.f, a2 = 0.f, a3 = 0.f;
#pragma unroll
            for (int m = 0; m < 4; m++) {
                float gm = s_g[lane + 32 * m];
                a0 += __ldg(&in_proj_w[i0 * Hn + lane + 32 * m]) * gm;
                a1 += __ldg(&in_proj_w[i1 * Hn + lane + 32 * m]) * gm;
                a2 += __ldg(&in_proj_w[i2 * Hn + lane + 32 * m]) * gm;
                a3 += __ldg(&in_proj_w[i3 * Hn + lane + 32 * m]) * gm;
            }
#pragma unroll
            for (int off = 16; off; off >>= 1) {
                a0 += __shfl_xor_sync(0xFFFFFFFFu, a0, off);
                a1 += __shfl_xor_sync(0xFFFFFFFFu, a1, off);
                a2 += __shfl_xor_sync(0xFFFFFFFFu, a2, off);
                a3 += __shfl_xor_sync(0xFFFFFFFFu, a3, off);
            }
            if (lane == 0) {
                s_q[i0] = a0 + in_proj_b[i0];
                s_q[i1] = a1 + in_proj_b[i1];
                s_q[i2] = a2 + in_proj_b[i2];
                s_q[i3] = a3 + in_proj_b[i3];
            }
        }
        __syncthreads();

#pragma unroll
        for (int k = 0; k < 2; k++) {     // p[n][c] — coalesced over c
            int o = tid + k * 256;
            int n = o >> 7, c = o & (Hn - 1);
            float acc = 0.f;
#pragma unroll 16
            for (int j = 0; j < 32; j++)
                acc += s_q[n * 32 + j] * __ldg(&in_proj_w[(Hn + n * 32 + j) * Hn + c]);
            s_p[n][c] = acc;
        }
        __syncthreads();

        {                                 // w[n][d]
            int n = tid >> 6, d = tid & 63;
            float acc = 0.f;
#pragma unroll 8
            for (int c = 0; c < Hn; c++) acc += s_p[n][c] * th[c * THS + d];
            g_w[b * (NHn * Dn) + tid] = acc * SCALE;
        }
    } else {
        const int r0 = (blockIdx.x - Bn) * 16;
        __shared__ float s_wv[16 * Hn];
        // s_wv staging: 512 float4, 2 per thread, in flight together
        {
            const float4* wv4 = (const float4*)(in_proj_w + (2 * Hn + r0) * Hn);
            float4 v0 = __ldg(&wv4[tid]);
            float4 v1 = __ldg(&wv4[tid + 256]);
            float4* s4 = (float4*)s_wv;
            s4[tid] = v0;
            s4[tid + 256] = v1;
        }
        __syncthreads();
#pragma unroll
        for (int k = 0; k < 4; k++) {
            int o = tid + k * 256;
            int h = o >> 6, d = o & 63;
            float acc = 0.f;
#pragma unroll 8
            for (int c = 0; c < Hn; c++)
                acc += s_wv[h * Hn + c] * th[c * THS + d];
            g_Vp[(r0 + h) * Dn + d] = acc;
        }
        if (tid < 16) {
            float acc = in_proj_b[2 * Hn + r0 + tid];
#pragma unroll 8
            for (int c = 0; c < Hn; c++)
                acc += s_wv[tid * Hn + c] * theta_b[c];
            g_vb[r0 + tid] = acc;
        }
    }
}

// ---------------------------------------------------------------------------
// score: grid (NS+1, Bn). s<NS = slice body; s==NS = dedicated tail block.
// ---------------------------------------------------------------------------
__global__ void __launch_bounds__(256) score_kernel(
    const float* __restrict__ x,
    const float* __restrict__ out_proj_w,
    const float* __restrict__ out_proj_b,
    const float* __restrict__ ln_g,
    const float* __restrict__ ln_b,
    const float* __restrict__ w1,
    const float* __restrict__ b1,
    const float* __restrict__ w2,
    const float* __restrict__ b2,
    float* __restrict__ out)
{
    const int s = blockIdx.x, b = blockIdx.y, tid = threadIdx.x;
    const int warp = tid >> 5, lane = tid & 31;

    __shared__ float xr[NR * RS];
    __shared__ float y[NHn][NR + 2];
    __shared__ float sc[NHn][SL];
    __shared__ float rsinv[SL];
    __shared__ float cc[NHn][NR];
    __shared__ float sw[NHn][Dn + 1];
    __shared__ float s_ML[NHn][2];
    __shared__ float s_u[NHn * Dn];
    __shared__ float s_o[Hn];
    __shared__ float s_a[Hn];
    __shared__ float s_hid[Hn];
    __shared__ float s_mv[2];

    if (s < NS) {
        // ===================== slice body (R12/R15 proven) =====================
        const int t0 = s * SL;
        {
            const float4* xb4 = (const float4*)&x[(size_t)b * Tn * Dn];
            float4 v[5];
            int idx[5];
#pragma unroll
            for (int k = 0; k < 5; k++) {
                int i = tid + k * 256;
                idx[k] = i;
                v[k] = make_float4(0.f, 0.f, 0.f, 0.f);
                if (i < NR * 16) {
                    int r = i >> 4, c4 = i & 15, gt = t0 - 3 + r;
                    if (gt >= 0 && gt < Tn) v[k] = __ldg(&xb4[gt * 16 + c4]);
                }
            }
#pragma unroll
            for (int k = 0; k < 5; k++) {
                int i = idx[k];
                if (i < NR * 16) {
                    int r = i >> 4, c4 = i & 15;
                    int base = r * RS + c4 * 4;
                    xr[base] = v[k].x; xr[base + 1] = v[k].y;
                    xr[base + 2] = v[k].z; xr[base + 3] = v[k].w;
                }
            }
        }
        sw[tid >> 6][tid & 63] = __ldg(&g_w[b * (NHn * Dn) + tid]);
        __syncthreads();

        for (int o = tid; o < NHn * NR; o += 256) {
            int n = o / NR, r = o - n * NR;
            float acc = 0.f;
#pragma unroll 8
            for (int d = 0; d < Dn; d++) acc += sw[n][d] * xr[r * RS + d];
            y[n][r] = acc;
        }
        __syncthreads();

        {
            int n = tid >> 6, t = tid & 63, tg = t0 + t;
            float acc = 0.f, ws = 0.f;
#pragma unroll
            for (int dd = -3; dd <= 3; dd++) {
                int tt = tg + dd;
                if (tt >= 0 && tt < Tn) {
                    float wv = 1.0f / (1.0f + (float)(dd < 0 ? -dd : dd));
                    ws += wv;
                    acc += wv * y[n][t + 3 + dd];
                }
            }
            float inv = __fdividef(1.0f, ws);
            sc[n][t] = acc * inv;
            if (n == 0) rsinv[t] = inv;
        }
        __syncthreads();

        if (tid < NHn * 32) {
            int n = tid >> 5;
            float v0 = sc[n][lane], v1 = sc[n][lane + 32];
            float m = fmaxf(v0, v1);
#pragma unroll
            for (int off = 16; off; off >>= 1)
                m = fmaxf(m, __shfl_xor_sync(0xFFFFFFFFu, m, off));
            float e0 = __expf(v0 - m), e1 = __expf(v1 - m);
            sc[n][lane] = e0; sc[n][lane + 32] = e1;
            float l = e0 + e1;
#pragma unroll
            for (int off = 16; off; off >>= 1)
                l += __shfl_xor_sync(0xFFFFFFFFu, l, off);
            if (lane == 0) {
                g_m[(b * NHn + n) * NS + s] = m;
                g_l[(b * NHn + n) * NS + s] = l;
            }
        }
        __syncthreads();

        for (int o = tid; o < NHn * NR; o += 256) {
            int n = o / NR, i = o - n * NR;
            int taug = t0 - 3 + i;
            float acc = 0.f;
            if (taug >= 0 && taug < Tn) {
#pragma unroll
                for (int dd = -3; dd <= 3; dd++) {
                    int j = i - 3 - dd;
                    if (j >= 0 && j < SL) {
                        float wv = 1.0f / (1.0f + (float)(dd < 0 ? -dd : dd));
                        acc += wv * sc[n][j] * rsinv[j];
                    }
                }
            }
            cc[n][i] = acc;
        }
        __syncthreads();

        {
            int n = tid >> 6, d = tid & 63;
            float acc = 0.f;
#pragma unroll 7
            for (int i = 0; i < NR; i++) acc += cc[n][i] * xr[i * RS + d];
            g_u[((b * NHn + n) * NS + s) * Dn + d] = acc;
        }

        __syncthreads();
        if (tid == 0) {
            __threadfence();
            atomicAdd(&g_cnt[b], 1u);
        }
        return;
    }

    // ===================== dedicated tail block (s == NS) =====================
    {
        const char* p1 = (const char*)out_proj_w;    // 64 KB
        const char* p2 = (const char*)w1;            // 64 KB
        const char* p3 = (const char*)g_Vp;          // 32 KB
        for (int i = tid; i < 512; i += 256) { l2_prefetch(p1 + i * 128); l2_prefetch(p2 + i * 128); }
        for (int i = tid; i < 256; i += 256) l2_prefetch(p3 + i * 128);
        if (tid < 8) {
            l2_prefetch((const char*)g_vb + tid * 64);
            l2_prefetch((const char*)out_proj_b + tid * 64);
            l2_prefetch((const char*)ln_g + tid * 64);
            l2_prefetch((const char*)ln_b + tid * 64);
            l2_prefetch((const char*)b1 + tid * 64);
            l2_prefetch((const char*)w2 + tid * 64);
        }
    }

    if (tid == 0) {
        volatile unsigned int* cnt = &g_cnt[b];
        while (*cnt < (unsigned)NS) __nanosleep(128);
    }
    __syncthreads();
    __threadfence();   // acquire

    if (tid < NHn) {
        float M = -1e30f;
#pragma unroll
        for (int k = 0; k < NS; k++) M = fmaxf(M, g_m[(b * NHn + tid) * NS + k]);
        float L = 0.f;
#pragma unroll
        for (int k = 0; k < NS; k++)
            L += g_l[(b * NHn + tid) * NS + k] *
                 __expf(g_m[(b * NHn + tid) * NS + k] - M);
        s_ML[tid][0] = M;
        s_ML[tid][1] = L;
    }
    __syncthreads();
    {
        int n = tid >> 6, d = tid & 63;
        float acc = 0.f;
#pragma unroll
        for (int k = 0; k < NS; k++)
            acc += g_u[((b * NHn + n) * NS + k) * Dn + d] *
                   __expf(g_m[(b * NHn + n) * NS + k] - s_ML[n][0]);
        s_u[n * Dn + d] = __fdividef(acc, s_ML[n][1]);
    }
    __syncthreads();

    // o[i] = vb[i] + Vp[i,:] . u[i/32] — 4-way interleaved warp-dots
#pragma unroll
    for (int gq = 0; gq < 4; gq++) {
        int i0 = warp + 8 * (4 * gq + 0);
        int i1 = warp + 8 * (4 * gq + 1);
        int i2 = warp + 8 * (4 * gq + 2);
        int i3 = warp + 8 * (4 * gq + 3);
        float a0 = 0.f, a1 = 0.f, a2 = 0.f, a3 = 0.f;
#pragma unroll
        for (int m = 0; m < 2; m++) {
            int c = lane + 32 * m;
            a0 += __ldg(&g_Vp[i0 * Dn + c]) * s_u[(i0 >> 5) * Dn + c];
            a1 += __ldg(&g_Vp[i1 * Dn + c]) * s_u[(i1 >> 5) * Dn + c];
            a2 += __ldg(&g_Vp[i2 * Dn + c]) * s_u[(i2 >> 5) * Dn + c];
            a3 += __ldg(&g_Vp[i3 * Dn + c]) * s_u[(i3 >> 5) * Dn + c];
        }
#pragma unroll
        for (int off = 16; off; off >>= 1) {
            a0 += __shfl_xor_sync(0xFFFFFFFFu, a0, off);
            a1 += __shfl_xor_sync(0xFFFFFFFFu, a1, off);
            a2 += __shfl_xor_sync(0xFFFFFFFFu, a2, off);
            a3 += __shfl_xor_sync(0xFFFFFFFFu, a3, off);
        }
        if (lane == 0) {
            s_o[i0] = a0 + g_vb[i0];
            s_o[i1] = a1 + g_vb[i1];
            s_o[i2] = a2 + g_vb[i2];
            s_o[i3] = a3 + g_vb[i3];
        }
    }
    __syncthreads();

    // a[i] = out_proj[i,:] . o + b — 4-way interleaved warp-dots
#pragma unroll
    for (int gq = 0; gq < 4; gq++) {
        int i0 = warp + 8 * (4 * gq + 0);
        int i1 = warp + 8 * (4 * gq + 1);
        int i2 = warp + 8 * (4 * gq + 2);
        int i3 = warp + 8 * (4 * gq + 3);
        float a0 = 0.f, a1 = 0.f, a2 = 0.f, a3 = 0.f;
#pragma unroll
        for (int m = 0; m < 4; m++) {
            float ov = s_o[lane + 32 * m];
            a0 += __ldg(&out_proj_w[i0 * Hn + lane + 32 * m]) * ov;
            a1 += __ldg(&out_proj_w[i1 * Hn + lane + 32 * m]) * ov;
            a2 += __ldg(&out_proj_w[i2 * Hn + lane + 32 * m]) * ov;
            a3 += __ldg(&out_proj_w[i3 * Hn + lane + 32 * m]) * ov;
        }
#pragma unroll
        for (int off = 16; off; off >>= 1) {
            a0 += __shfl_xor_sync(0xFFFFFFFFu, a0, off);
            a1 += __shfl_xor_sync(0xFFFFFFFFu, a1, off);
            a2 += __shfl_xor_sync(0xFFFFFFFFu, a2, off);
            a3 += __shfl_xor_sync(0xFFFFFFFFu, a3, off);
        }
        if (lane == 0) {
            s_a[i0] = a0 + out_proj_b[i0];
            s_a[i1] = a1 + out_proj_b[i1];
            s_a[i2] = a2 + out_proj_b[i2];
            s_a[i3] = a3 + out_proj_b[i3];
        }
    }
    __syncthreads();

    // LayerNorm over 128
    if (tid < 32) {
        float sum = s_a[tid] + s_a[tid + 32] + s_a[tid + 64] + s_a[tid + 96];
#pragma unroll
        for (int off = 16; off; off >>= 1)
            sum += __shfl_xor_sync(0xFFFFFFFFu, sum, off);
        if (tid == 0) s_mv[0] = sum * (1.0f / Hn);
    }
    __syncthreads();
    if (tid < 32) {
        float mu = s_mv[0], sum = 0.f;
#pragma unroll
        for (int k = 0; k < 4; k++) {
            float d = s_a[tid + 32 * k] - mu;
            sum += d * d;
        }
#pragma unroll
        for (int off = 16; off; off >>= 1)
            sum += __shfl_xor_sync(0xFFFFFFFFu, sum, off);
        if (tid == 0) s_mv[1] = sum * (1.0f / Hn);
    }
    __syncthreads();
    if (tid < Hn) {
        float inv = rsqrtf(s_mv[1] + 1e-5f);
        s_a[tid] = (s_a[tid] - s_mv[0]) * inv * ln_g[tid] + ln_b[tid];
    }
    __syncthreads();

    // hid = gelu(w1 @ ln + b1) — 4-way interleaved warp-dots
#pragma unroll
    for (int gq = 0; gq < 4; gq++) {
        int i0 = warp + 8 * (4 * gq + 0);
        int i1 = warp + 8 * (4 * gq + 1);
        int i2 = warp + 8 * (4 * gq + 2);
        int i3 = warp + 8 * (4 * gq + 3);
        float a0 = 0.f, a1 = 0.f, a2 = 0.f, a3 = 0.f;
#pragma unroll
        for (int m = 0; m < 4; m++) {
            float lv = s_a[lane + 32 * m];
            a0 += __ldg(&w1[i0 * Hn + lane + 32 * m]) * lv;
            a1 += __ldg(&w1[i1 * Hn + lane + 32 * m]) * lv;
            a2 += __ldg(&w1[i2 * Hn + lane + 32 * m]) * lv;
            a3 += __ldg(&w1[i3 * Hn + lane + 32 * m]) * lv;
        }
#pragma unroll
        for (int off = 16; off; off >>= 1) {
            a0 += __shfl_xor_sync(0xFFFFFFFFu, a0, off);
            a1 += __shfl_xor_sync(0xFFFFFFFFu, a1, off);
            a2 += __shfl_xor_sync(0xFFFFFFFFu, a2, off);
            a3 += __shfl_xor_sync(0xFFFFFFFFu, a3, off);
        }
        if (lane == 0) {
            float v0 = a0 + b1[i0], v1 = a1 + b1[i1];
            float v2 = a2 + b1[i2], v3 = a3 + b1[i3];
            s_hid[i0] = 0.5f * v0 * (1.0f + erff(v0 * 0.70710678118654752f));
            s_hid[i1] = 0.5f * v1 * (1.0f + erff(v1 * 0.70710678118654752f));
            s_hid[i2] = 0.5f * v2 * (1.0f + erff(v2 * 0.70710678118654752f));
            s_hid[i3] = 0.5f * v3 * (1.0f + erff(v3 * 0.70710678118654752f));
        }
    }
    __syncthreads();

    if (warp < 2) {
        float acc = 0.f;
#pragma unroll
        for (int m = 0; m < 4; m++)
            acc += __ldg(&w2[warp * Hn + lane + 32 * m]) * s_hid[lane + 32 * m];
#pragma unroll
        for (int off = 16; off; off >>= 1)
            acc += __shfl_xor_sync(0xFFFFFFFFu, acc, off);
        if (lane == 0) out[b * 2 + warp] = acc + b2[warp];
    }

    // reset counter for next graph replay
    __syncthreads();
    if (tid == 0) g_cnt[b] = 0u;
}

// ---------------------------------------------------------------------------
extern "C" void kernel_launch(void* const* d_in, const int* in_sizes, int n_in,
                              void* d_out, int out_size) {
    const float* x          = (const float*)d_in[0];
    const float* theta_w    = (const float*)d_in[1];
    const float* theta_b    = (const float*)d_in[2];
    const float* in_proj_w  = (const float*)d_in[3];
    const float* in_proj_b  = (const float*)d_in[4];
    const float* out_proj_w = (const float*)d_in[5];
    const float* out_proj_b = (const float*)d_in[6];
    const float* lng        = (const float*)d_in[7];
    const float* lnb        = (const float*)d_in[8];
    const float* w1         = (const float*)d_in[9];
    const float* b1         = (const float*)d_in[10];
    const float* w2         = (const float*)d_in[11];
    const float* b2         = (const float*)d_in[12];
    float* out = (float*)d_out;

    pre_kernel<<<40, 256>>>(x, theta_w, theta_b, in_proj_w, in_proj_b);
    score_kernel<<<dim3(NS + 1, Bn), 256>>>(x, out_proj_w, out_proj_b,
                                            lng, lnb, w1, b1, w2, b2, out);
}

// round 17
// speedup vs baseline: 1.3322x; 1.1119x over previous
#include <cuda_runtime.h>
#include <math.h>

// GraphTemporalRefiner — R16 (best) + float4 smem traffic in the slice body
// (y-dots and u_part move from scalar LDS to LDS.128; u_part chain split 4x).
//   y[b,n,t] = w[b,n] . x[b,t];  score_t = (1/rs) sum wv*y_{t+dd}
//   u_part   = sum_tau c_tau x_tau   (c = transpose-conv of phat/rs)
//   tail: o = Vp u + vb; a = out_proj o; LN; gelu MLP -> out (B,2)
// pre (grid 40): per-batch w chain + Vp/vb folding.
// score (grid (NS+1) x 32): s<NS slice blocks; s==NS prefetching tail block.

namespace {
constexpr int Bn  = 32;
constexpr int Tn  = 1024;
constexpr int Dn  = 64;
constexpr int Hn  = 128;
constexpr int NHn = 4;
constexpr int SL  = 64;
constexpr int NS  = Tn / SL;    // 16
constexpr int NR  = SL + 6;     // 70 rows incl. halo
constexpr int RS  = 68;         // xr row stride in floats (17 float4; 4r%32 distinct)
constexpr int RS4 = 17;         // xr row stride in float4
constexpr int THS = Dn + 1;     // padded theta row stride (65)
}

__device__ __align__(16) float g_w[Bn * NHn * Dn];
__device__ __align__(16) float g_Vp[Hn * Dn];
__device__ float g_vb[Hn];
__device__ float g_m[Bn * NHn * NS];
__device__ float g_l[Bn * NHn * NS];
__device__ __align__(16) float g_u[Bn * NHn * NS * Dn];
__device__ unsigned int g_cnt[Bn];

__device__ __forceinline__ void l2_prefetch(const void* p) {
    asm volatile("prefetch.global.L2 [%0];" :: "l"(p));
}

// ---------------------------------------------------------------------------
// pre: blocks 0..31 -> w[b]; blocks 32..39 -> Vp rows (16 each) + vb.
// (byte-identical to R16)
// ---------------------------------------------------------------------------
__global__ void __launch_bounds__(256) pre_kernel(
    const float* __restrict__ x,
    const float* __restrict__ theta_w,    // (128, 64)
    const float* __restrict__ theta_b,
    const float* __restrict__ in_proj_w,  // (384, 128)
    const float* __restrict__ in_proj_b)
{
    const int tid = threadIdx.x;
    const int warp = tid >> 5, lane = tid & 31;
    const float SCALE = 0.17677669529663687f;   // 1/sqrt(32)

    __shared__ float th[Hn * THS];

    {
        const float4* th4 = (const float4*)theta_w;
        float4 v[8];
#pragma unroll
        for (int k = 0; k < 8; k++) v[k] = __ldg(&th4[tid + k * 256]);
#pragma unroll
        for (int k = 0; k < 8; k++) {
            int i = tid + k * 256;
            int r = i >> 4, c = (i & 15) * 4;
            int base = r * THS + c;
            th[base] = v[k].x; th[base + 1] = v[k].y;
            th[base + 2] = v[k].z; th[base + 3] = v[k].w;
        }
    }

    if (blockIdx.x < Bn) {
        const int b = blockIdx.x;
        __shared__ float sxl[Dn];
        __shared__ float s_g[Hn];
        __shared__ float s_q[Hn];
        __shared__ float s_p[NHn][Hn];

        if (tid == 0) g_cnt[b] = 0u;

        if (tid < Dn) {
            float sum = 0.f, ws = 0.f;
#pragma unroll
            for (int dd = 0; dd < 4; dd++) {
                float wv = 1.0f / (1.0f + (float)dd);
                ws += wv;
                sum += wv * __ldg(&x[((size_t)b * Tn + (Tn - 1 - dd)) * Dn + tid]);
            }
            sxl[tid] = __fdividef(sum, ws);
        }
        __syncthreads();

        if (tid < Hn) {
            float acc = theta_b[tid];
#pragma unroll 8
            for (int d = 0; d < Dn; d++) acc += th[tid * THS + d] * sxl[d];
            s_g[tid] = acc;
        }
        __syncthreads();

#pragma unroll
        for (int gq = 0; gq < 4; gq++) {
            int i0 = warp + 8 * (4 * gq + 0);
            int i1 = warp + 8 * (4 * gq + 1);
            int i2 = warp + 8 * (4 * gq + 2);
            int i3 = warp + 8 * (4 * gq + 3);
            float a0 = 0.f, a1 = 0.f, a2 = 0.f, a3 = 0.f;
#pragma unroll
            for (int m = 0; m < 4; m++) {
                float gm = s_g[lane + 32 * m];
                a0 += __ldg(&in_proj_w[i0 * Hn + lane + 32 * m]) * gm;
                a1 += __ldg(&in_proj_w[i1 * Hn + lane + 32 * m]) * gm;
                a2 += __ldg(&in_proj_w[i2 * Hn + lane + 32 * m]) * gm;
                a3 += __ldg(&in_proj_w[i3 * Hn + lane + 32 * m]) * gm;
            }
#pragma unroll
            for (int off = 16; off; off >>= 1) {
                a0 += __shfl_xor_sync(0xFFFFFFFFu, a0, off);
                a1 += __shfl_xor_sync(0xFFFFFFFFu, a1, off);
                a2 += __shfl_xor_sync(0xFFFFFFFFu, a2, off);
                a3 += __shfl_xor_sync(0xFFFFFFFFu, a3, off);
            }
            if (lane == 0) {
                s_q[i0] = a0 + in_proj_b[i0];
                s_q[i1] = a1 + in_proj_b[i1];
                s_q[i2] = a2 + in_proj_b[i2];
                s_q[i3] = a3 + in_proj_b[i3];
            }
        }
        __syncthreads();

#pragma unroll
        for (int k = 0; k < 2; k++) {
            int o = tid + k * 256;
            int n = o >> 7, c = o & (Hn - 1);
            float acc = 0.f;
#pragma unroll 16
            for (int j = 0; j < 32; j++)
                acc += s_q[n * 32 + j] * __ldg(&in_proj_w[(Hn + n * 32 + j) * Hn + c]);
            s_p[n][c] = acc;
        }
        __syncthreads();

        {
            int n = tid >> 6, d = tid & 63;
            float acc = 0.f;
#pragma unroll 8
            for (int c = 0; c < Hn; c++) acc += s_p[n][c] * th[c * THS + d];
            g_w[b * (NHn * Dn) + tid] = acc * SCALE;
        }
    } else {
        const int r0 = (blockIdx.x - Bn) * 16;
        __shared__ float s_wv[16 * Hn];
        {
            const float4* wv4 = (const float4*)(in_proj_w + (2 * Hn + r0) * Hn);
            float4 v0 = __ldg(&wv4[tid]);
            float4 v1 = __ldg(&wv4[tid + 256]);
            float4* s4 = (float4*)s_wv;
            s4[tid] = v0;
            s4[tid + 256] = v1;
        }
        __syncthreads();
#pragma unroll
        for (int k = 0; k < 4; k++) {
            int o = tid + k * 256;
            int h = o >> 6, d = o & 63;
            float acc = 0.f;
#pragma unroll 8
            for (int c = 0; c < Hn; c++)
                acc += s_wv[h * Hn + c] * th[c * THS + d];
            g_Vp[(r0 + h) * Dn + d] = acc;
        }
        if (tid < 16) {
            float acc = in_proj_b[2 * Hn + r0 + tid];
#pragma unroll 8
            for (int c = 0; c < Hn; c++)
                acc += s_wv[tid * Hn + c] * theta_b[c];
            g_vb[r0 + tid] = acc;
        }
    }
}

// ---------------------------------------------------------------------------
// score: grid (NS+1, Bn). s<NS = slice body; s==NS = dedicated tail block.
// ---------------------------------------------------------------------------
__global__ void __launch_bounds__(256) score_kernel(
    const float* __restrict__ x,
    const float* __restrict__ out_proj_w,
    const float* __restrict__ out_proj_b,
    const float* __restrict__ ln_g,
    const float* __restrict__ ln_b,
    const float* __restrict__ w1,
    const float* __restrict__ b1,
    const float* __restrict__ w2,
    const float* __restrict__ b2,
    float* __restrict__ out)
{
    const int s = blockIdx.x, b = blockIdx.y, tid = threadIdx.x;
    const int warp = tid >> 5, lane = tid & 31;

    __shared__ __align__(16) float xr[NR * RS];   // 70 x 68 floats
    __shared__ float y[NHn][NR + 2];
    __shared__ float sc[NHn][SL];
    __shared__ float rsinv[SL];
    __shared__ float cc[NHn][NR];
    __shared__ float sw[NHn][Dn + 1];
    __shared__ float4 su4[4][NHn][16];            // u_part chunk partials (4 KB)
    __shared__ float s_ML[NHn][2];
    __shared__ float s_u[NHn * Dn];
    __shared__ float s_o[Hn];
    __shared__ float s_a[Hn];
    __shared__ float s_hid[Hn];
    __shared__ float s_mv[2];

    if (s < NS) {
        // ===================== slice body =====================
        const int t0 = s * SL;

        // stage raw x rows -> float4 rows (stride 17 float4); OOB zeroed.
        {
            const float4* xb4 = (const float4*)&x[(size_t)b * Tn * Dn];
            float4* xr4 = (float4*)xr;
            float4 v[5];
            int idx[5];
#pragma unroll
            for (int k = 0; k < 5; k++) {
                int i = tid + k * 256;
                idx[k] = i;
                v[k] = make_float4(0.f, 0.f, 0.f, 0.f);
                if (i < NR * 16) {
                    int r = i >> 4, c4 = i & 15, gt = t0 - 3 + r;
                    if (gt >= 0 && gt < Tn) v[k] = __ldg(&xb4[gt * 16 + c4]);
                }
            }
#pragma unroll
            for (int k = 0; k < 5; k++) {
                int i = idx[k];
                if (i < NR * 16) {
                    int r = i >> 4, c4 = i & 15;
                    xr4[r * RS4 + c4] = v[k];
                }
            }
        }
        sw[tid >> 6][tid & 63] = __ldg(&g_w[b * (NHn * Dn) + tid]);
        __syncthreads();

        // y[n][r] = w[n] . xr[r] — float4 row dots (16 LDS.128 each)
        for (int o = tid; o < NHn * NR; o += 256) {
            int n = o / NR, r = o - n * NR;
            const float4* row = (const float4*)&xr[r * RS];
            float acc = 0.f;
#pragma unroll
            for (int k = 0; k < 16; k++) {
                float4 v = row[k];
                acc += sw[n][k * 4 + 0] * v.x + sw[n][k * 4 + 1] * v.y +
                       sw[n][k * 4 + 2] * v.z + sw[n][k * 4 + 3] * v.w;
            }
            y[n][r] = acc;
        }
        __syncthreads();

        // score_t = (1/rs) sum_dd wv y[t+3+dd]
        {
            int n = tid >> 6, t = tid & 63, tg = t0 + t;
            float acc = 0.f, ws = 0.f;
#pragma unroll
            for (int dd = -3; dd <= 3; dd++) {
                int tt = tg + dd;
                if (tt >= 0 && tt < Tn) {
                    float wv = 1.0f / (1.0f + (float)(dd < 0 ? -dd : dd));
                    ws += wv;
                    acc += wv * y[n][t + 3 + dd];
                }
            }
            float inv = __fdividef(1.0f, ws);
            sc[n][t] = acc * inv;
            if (n == 0) rsinv[t] = inv;
        }
        __syncthreads();

        // slice softmax partials: warp n = head n
        if (tid < NHn * 32) {
            int n = tid >> 5;
            float v0 = sc[n][lane], v1 = sc[n][lane + 32];
            float m = fmaxf(v0, v1);
#pragma unroll
            for (int off = 16; off; off >>= 1)
                m = fmaxf(m, __shfl_xor_sync(0xFFFFFFFFu, m, off));
            float e0 = __expf(v0 - m), e1 = __expf(v1 - m);
            sc[n][lane] = e0; sc[n][lane + 32] = e1;
            float l = e0 + e1;
#pragma unroll
            for (int off = 16; off; off >>= 1)
                l += __shfl_xor_sync(0xFFFFFFFFu, l, off);
            if (lane == 0) {
                g_m[(b * NHn + n) * NS + s] = m;
                g_l[(b * NHn + n) * NS + s] = l;
            }
        }
        __syncthreads();

        // c[n][i] = transpose-conv of phat*rsinv
        for (int o = tid; o < NHn * NR; o += 256) {
            int n = o / NR, i = o - n * NR;
            int taug = t0 - 3 + i;
            float acc = 0.f;
            if (taug >= 0 && taug < Tn) {
#pragma unroll
                for (int dd = -3; dd <= 3; dd++) {
                    int j = i - 3 - dd;
                    if (j >= 0 && j < SL) {
                        float wv = 1.0f / (1.0f + (float)(dd < 0 ? -dd : dd));
                        acc += wv * sc[n][j] * rsinv[j];
                    }
                }
            }
            cc[n][i] = acc;
        }
        __syncthreads();

        // u_part: 256 threads = 4 chunks x 4 heads x 16 d-quads, float4 rows
        {
            int q = tid >> 6;                 // row chunk
            int n = (tid >> 4) & 3;           // head
            int d4 = tid & 15;                // d quad
            int i0 = (q * NR) >> 2;           // 0,17,35,52
            int i1 = ((q + 1) * NR) >> 2;     // 17,35,52,70
            const float4* xr4 = (const float4*)xr;
            float4 acc = make_float4(0.f, 0.f, 0.f, 0.f);
#pragma unroll 6
            for (int i = i0; i < i1; i++) {
                float c = cc[n][i];
                float4 v = xr4[i * RS4 + d4];
                acc.x += c * v.x; acc.y += c * v.y;
                acc.z += c * v.z; acc.w += c * v.w;
            }
            su4[q][n][d4] = acc;
        }
        __syncthreads();
        if (tid < 64) {
            int n = tid >> 4, d4 = tid & 15;
            float4 a0 = su4[0][n][d4], a1 = su4[1][n][d4];
            float4 a2 = su4[2][n][d4], a3 = su4[3][n][d4];
            float4 r;
            r.x = a0.x + a1.x + a2.x + a3.x;
            r.y = a0.y + a1.y + a2.y + a3.y;
            r.z = a0.z + a1.z + a2.z + a3.z;
            r.w = a0.w + a1.w + a2.w + a3.w;
            ((float4*)&g_u[((b * NHn + n) * NS + s) * Dn])[d4] = r;
        }

        // release: syncthreads orders all stores, tid0 fence+atomic publishes.
        __syncthreads();
        if (tid == 0) {
            __threadfence();
            atomicAdd(&g_cnt[b], 1u);
        }
        return;
    }

    // ===================== dedicated tail block (s == NS) =====================
    {
        const char* p1 = (const char*)out_proj_w;    // 64 KB
        const char* p2 = (const char*)w1;            // 64 KB
        const char* p3 = (const char*)g_Vp;          // 32 KB
        for (int i = tid; i < 512; i += 256) { l2_prefetch(p1 + i * 128); l2_prefetch(p2 + i * 128); }
        for (int i = tid; i < 256; i += 256) l2_prefetch(p3 + i * 128);
        if (tid < 8) {
            l2_prefetch((const char*)g_vb + tid * 64);
            l2_prefetch((const char*)out_proj_b + tid * 64);
            l2_prefetch((const char*)ln_g + tid * 64);
            l2_prefetch((const char*)ln_b + tid * 64);
            l2_prefetch((const char*)b1 + tid * 64);
            l2_prefetch((const char*)w2 + tid * 64);
        }
    }

    if (tid == 0) {
        volatile unsigned int* cnt = &g_cnt[b];
        while (*cnt < (unsigned)NS) __nanosleep(128);
    }
    __syncthreads();
    __threadfence();   // acquire

    if (tid < NHn) {
        float M = -1e30f;
#pragma unroll
        for (int k = 0; k < NS; k++) M = fmaxf(M, g_m[(b * NHn + tid) * NS + k]);
        float L = 0.f;
#pragma unroll
        for (int k = 0; k < NS; k++)
            L += g_l[(b * NHn + tid) * NS + k] *
                 __expf(g_m[(b * NHn + tid) * NS + k] - M);
        s_ML[tid][0] = M;
        s_ML[tid][1] = L;
    }
    __syncthreads();
    {
        int n = tid >> 6, d = tid & 63;
        float acc = 0.f;
#pragma unroll
        for (int k = 0; k < NS; k++)
            acc += g_u[((b * NHn + n) * NS + k) * Dn + d] *
                   __expf(g_m[(b * NHn + n) * NS + k] - s_ML[n][0]);
        s_u[n * Dn + d] = __fdividef(acc, s_ML[n][1]);
    }
    __syncthreads();

    // o[i] = vb[i] + Vp[i,:] . u[i/32] — 4-way interleaved warp-dots
#pragma unroll
    for (int gq = 0; gq < 4; gq++) {
        int i0 = warp + 8 * (4 * gq + 0);
        int i1 = warp + 8 * (4 * gq + 1);
        int i2 = warp + 8 * (4 * gq + 2);
        int i3 = warp + 8 * (4 * gq + 3);
        float a0 = 0.f, a1 = 0.f, a2 = 0.f, a3 = 0.f;
#pragma unroll
        for (int m = 0; m < 2; m++) {
            int c = lane + 32 * m;
            a0 += __ldg(&g_Vp[i0 * Dn + c]) * s_u[(i0 >> 5) * Dn + c];
            a1 += __ldg(&g_Vp[i1 * Dn + c]) * s_u[(i1 >> 5) * Dn + c];
            a2 += __ldg(&g_Vp[i2 * Dn + c]) * s_u[(i2 >> 5) * Dn + c];
            a3 += __ldg(&g_Vp[i3 * Dn + c]) * s_u[(i3 >> 5) * Dn + c];
        }
#pragma unroll
        for (int off = 16; off; off >>= 1) {
            a0 += __shfl_xor_sync(0xFFFFFFFFu, a0, off);
            a1 += __shfl_xor_sync(0xFFFFFFFFu, a1, off);
            a2 += __shfl_xor_sync(0xFFFFFFFFu, a2, off);
            a3 += __shfl_xor_sync(0xFFFFFFFFu, a3, off);
        }
        if (lane == 0) {
            s_o[i0] = a0 + g_vb[i0];
            s_o[i1] = a1 + g_vb[i1];
            s_o[i2] = a2 + g_vb[i2];
            s_o[i3] = a3 + g_vb[i3];
        }
    }
    __syncthreads();

    // a[i] = out_proj[i,:] . o + b — 4-way interleaved warp-dots
#pragma unroll
    for (int gq = 0; gq < 4; gq++) {
        int i0 = warp + 8 * (4 * gq + 0);
        int i1 = warp + 8 * (4 * gq + 1);
        int i2 = warp + 8 * (4 * gq + 2);
        int i3 = warp + 8 * (4 * gq + 3);
        float a0 = 0.f, a1 = 0.f, a2 = 0.f, a3 = 0.f;
#pragma unroll
        for (int m = 0; m < 4; m++) {
            float ov = s_o[lane + 32 * m];
            a0 += __ldg(&out_proj_w[i0 * Hn + lane + 32 * m]) * ov;
            a1 += __ldg(&out_proj_w[i1 * Hn + lane + 32 * m]) * ov;
            a2 += __ldg(&out_proj_w[i2 * Hn + lane + 32 * m]) * ov;
            a3 += __ldg(&out_proj_w[i3 * Hn + lane + 32 * m]) * ov;
        }
#pragma unroll
        for (int off = 16; off; off >>= 1) {
            a0 += __shfl_xor_sync(0xFFFFFFFFu, a0, off);
            a1 += __shfl_xor_sync(0xFFFFFFFFu, a1, off);
            a2 += __shfl_xor_sync(0xFFFFFFFFu, a2, off);
            a3 += __shfl_xor_sync(0xFFFFFFFFu, a3, off);
        }
        if (lane == 0) {
            s_a[i0] = a0 + out_proj_b[i0];
            s_a[i1] = a1 + out_proj_b[i1];
            s_a[i2] = a2 + out_proj_b[i2];
            s_a[i3] = a3 + out_proj_b[i3];
        }
    }
    __syncthreads();

    // LayerNorm over 128
    if (tid < 32) {
        float sum = s_a[tid] + s_a[tid + 32] + s_a[tid + 64] + s_a[tid + 96];
#pragma unroll
        for (int off = 16; off; off >>= 1)
            sum += __shfl_xor_sync(0xFFFFFFFFu, sum, off);
        if (tid == 0) s_mv[0] = sum * (1.0f / Hn);
    }
    __syncthreads();
    if (tid < 32) {
        float mu = s_mv[0], sum = 0.f;
#pragma unroll
        for (int k = 0; k < 4; k++) {
            float d = s_a[tid + 32 * k] - mu;
            sum += d * d;
        }
#pragma unroll
        for (int off = 16; off; off >>= 1)
            sum += __shfl_xor_sync(0xFFFFFFFFu, sum, off);
        if (tid == 0) s_mv[1] = sum * (1.0f / Hn);
    }
    __syncthreads();
    if (tid < Hn) {
        float inv = rsqrtf(s_mv[1] + 1e-5f);
        s_a[tid] = (s_a[tid] - s_mv[0]) * inv * ln_g[tid] + ln_b[tid];
    }
    __syncthreads();

    // hid = gelu(w1 @ ln + b1) — 4-way interleaved warp-dots
#pragma unroll
    for (int gq = 0; gq < 4; gq++) {
        int i0 = warp + 8 * (4 * gq + 0);
        int i1 = warp + 8 * (4 * gq + 1);
        int i2 = warp + 8 * (4 * gq + 2);
        int i3 = warp + 8 * (4 * gq + 3);
        float a0 = 0.f, a1 = 0.f, a2 = 0.f, a3 = 0.f;
#pragma unroll
        for (int m = 0; m < 4; m++) {
            float lv = s_a[lane + 32 * m];
            a0 += __ldg(&w1[i0 * Hn + lane + 32 * m]) * lv;
            a1 += __ldg(&w1[i1 * Hn + lane + 32 * m]) * lv;
            a2 += __ldg(&w1[i2 * Hn + lane + 32 * m]) * lv;
            a3 += __ldg(&w1[i3 * Hn + lane + 32 * m]) * lv;
        }
#pragma unroll
        for (int off = 16; off; off >>= 1) {
            a0 += __shfl_xor_sync(0xFFFFFFFFu, a0, off);
            a1 += __shfl_xor_sync(0xFFFFFFFFu, a1, off);
            a2 += __shfl_xor_sync(0xFFFFFFFFu, a2, off);
            a3 += __shfl_xor_sync(0xFFFFFFFFu, a3, off);
        }
        if (lane == 0) {
            float v0 = a0 + b1[i0], v1 = a1 + b1[i1];
            float v2 = a2 + b1[i2], v3 = a3 + b1[i3];
            s_hid[i0] = 0.5f * v0 * (1.0f + erff(v0 * 0.70710678118654752f));
            s_hid[i1] = 0.5f * v1 * (1.0f + erff(v1 * 0.70710678118654752f));
            s_hid[i2] = 0.5f * v2 * (1.0f + erff(v2 * 0.70710678118654752f));
            s_hid[i3] = 0.5f * v3 * (1.0f + erff(v3 * 0.70710678118654752f));
        }
    }
    __syncthreads();

    if (warp < 2) {
        float acc = 0.f;
#pragma unroll
        for (int m = 0; m < 4; m++)
            acc += __ldg(&w2[warp * Hn + lane + 32 * m]) * s_hid[lane + 32 * m];
#pragma unroll
        for (int off = 16; off; off >>= 1)
            acc += __shfl_xor_sync(0xFFFFFFFFu, acc, off);
        if (lane == 0) out[b * 2 + warp] = acc + b2[warp];
    }

    // reset counter for next graph replay
    __syncthreads();
    if (tid == 0) g_cnt[b] = 0u;
}

// ---------------------------------------------------------------------------
extern "C" void kernel_launch(void* const* d_in, const int* in_sizes, int n_in,
                              void* d_out, int out_size) {
    const float* x          = (const float*)d_in[0];
    const float* theta_w    = (const float*)d_in[1];
    const float* theta_b    = (const float*)d_in[2];
    const float* in_proj_w  = (const float*)d_in[3];
    const float* in_proj_b  = (const float*)d_in[4];
    const float* out_proj_w = (const float*)d_in[5];
    const float* out_proj_b = (const float*)d_in[6];
    const float* lng        = (const float*)d_in[7];
    const float* lnb        = (const float*)d_in[8];
    const float* w1         = (const float*)d_in[9];
    const float* b1         = (const float*)d_in[10];
    const float* w2         = (const float*)d_in[11];
    const float* b2         = (const float*)d_in[12];
    float* out = (float*)d_out;

    pre_kernel<<<40, 256>>>(x, theta_w, theta_b, in_proj_w, in_proj_b);
    score_kernel<<<dim3(NS + 1, Bn), 256>>>(x, out_proj_w, out_proj_b,
                                            lng, lnb, w1, b1, w2, b2, out);
}